// round 16
// baseline (speedup 1.0000x reference)
#include <cuda_runtime.h>
#include <cuda_fp16.h>
#include <cstdint>

#define NB 256   // batch
#define ND 16    // manifold dim
#define NH 128   // hidden

__device__ __forceinline__ __half2 tanh2h(__half2 x) {
    uint32_t xi, yi;
    xi = *reinterpret_cast<uint32_t*>(&x);
    asm("tanh.approx.f16x2 %0, %1;" : "=r"(yi) : "r"(xi));
    __half2 y = *reinterpret_cast<__half2*>(&yi);
    return y;
}
__device__ __forceinline__ __half2 u2h2(uint32_t u) {
    return *reinterpret_cast<__half2*>(&u);
}

struct WPack { __half2 w0, w1, w2, b; };   // 16 bytes

// ============================================================================
// K_ALL: one block per batch element b. 512 threads = (hi = t>>8, o = t&255).
// Each half owns 8 i's, processed in 2 chunks of 4 (register relief WITHOUT
// persistent 8-wide arrays: pm lives in smem pms). 2 blocks/SM -> single wave.
// ============================================================================
__global__ __launch_bounds__(512, 2) void k_all(
    const float* __restrict__ points,
    const float* __restrict__ mW1, const float* __restrict__ mb1,
    const float* __restrict__ mW2, const float* __restrict__ mb2,
    const float* __restrict__ cW1, const float* __restrict__ cb1,
    const float* __restrict__ cW2, const float* __restrict__ cb2,
    const float* __restrict__ rW1, const float* __restrict__ rb1,
    const float* __restrict__ rW2, const float* __restrict__ rb2,
    float* __restrict__ out)
{
    int b  = blockIdx.x;
    int t  = threadIdx.x;   // 0..511
    int o  = t & 255;
    int hi = t >> 8;        // 0 or 1

    __shared__ float pts[ND];
    __shared__ float mh[NH];
    __shared__ float met[256];
    __shared__ float buf[256];            // mraw, later raw
    __shared__ float red[2][256];         // phase partials (reused 3x)
    __shared__ float Ss[256];
    __shared__ __align__(16) WPack   sW[NH / 2];
    __shared__ __align__(4)  __half2 sV[NH / 2];
    __shared__ float pms[ND][256];        // pm[i][o] = PB + M1
    __shared__ float m2s[ND][256];        // M2[j][o]
    __shared__ __align__(16) __half  chs[ND][256];

    // ---- P0: points ----
    if (t < ND) pts[t] = points[b * ND + t];
    __syncthreads();

    // ---- P1: metric hidden || weight conversion ----
    if (t < NH) {
        float a = mb1[t];
        #pragma unroll
        for (int p = 0; p < ND; p++) a = fmaf(pts[p], mW1[p * NH + t], a);
        mh[t] = fmaxf(a, 0.0f);
    } else if (t < NH + 64) {
        int q = t - NH;
        WPack w;
        w.w0 = __floats2half2_rn(cW1[2 * q],          cW1[2 * q + 1]);
        w.w1 = __floats2half2_rn(cW1[NH + 2 * q],     cW1[NH + 2 * q + 1]);
        w.w2 = __floats2half2_rn(cW1[2 * NH + 2 * q], cW1[2 * NH + 2 * q + 1]);
        w.b  = __floats2half2_rn(cb1[2 * q],          cb1[2 * q + 1]);
        sW[q] = w;
        sV[q] = __floats2half2_rn(cW2[2 * q], cW2[2 * q + 1]);
    }
    __syncthreads();

    // ---- P2: metric GEMM (h in [hi*64, hi*64+64), 2 interleaved chains) ----
    {
        int h0 = hi * 64;
        float a0 = 0.f, a1 = 0.f;
        #pragma unroll 8
        for (int h = 0; h < 32; h++) {
            a0 = fmaf(mh[h0 + h],      mW2[(h0 + h) * 256 + o],      a0);
            a1 = fmaf(mh[h0 + 32 + h], mW2[(h0 + 32 + h) * 256 + o], a1);
        }
        red[hi][o] = a0 + a1;
    }
    __syncthreads();
    if (t < 256) buf[t] = mb2[t] + red[0][t] + red[1][t];
    __syncthreads();
    if (t < 256) {
        int i = t >> 4, j = t & 15;
        met[t] = 0.5f * (buf[i * 16 + j] + buf[j * 16 + i])
               + (i == j ? 1e-6f : 0.0f);
    }
    __syncthreads();

    // ---- P3: pms[i][o] and m2s[j][o] for own half (inline rW1 loads,
    //          NO register arrays). Covered by P4's syncthreads. ----
    {
        float pb = rb1[o];
        #pragma unroll
        for (int p = 0; p < ND; p++) pb = fmaf(pts[p], rW1[p * 256 + o], pb);
        #pragma unroll
        for (int ii = 0; ii < 8; ii++) {
            int i = hi * 8 + ii;
            float a = 0.0f;
            #pragma unroll
            for (int p = 0; p < ND; p++)
                a = fmaf(met[i * 16 + p], rW1[(16 + p) * 256 + o], a);
            pms[i][o] = pb + a;
        }
        #pragma unroll
        for (int jj = 0; jj < 8; jj++) {
            int j = hi * 8 + jj;
            float a = 0.0f;
            #pragma unroll
            for (int p = 0; p < ND; p++)
                a = fmaf(met[j * 16 + p], rW1[(32 + p) * 256 + o], a);
            m2s[j][o] = a;
        }
    }

    // ---- P4 Stage A: christoffel, 2 chunks of 4 i's ----
    {
        int j = o >> 4, k = o & 15;
        __half2 mjk2 = __float2half2_rn(met[j * 16 + k]);
        const __half2 z2 = __float2half2_rn(0.0f);
        float c0 = cb2[0];

        #pragma unroll
        for (int c = 0; c < 2; c++) {
            int ib = hi * 8 + c * 4;
            __half2 mij2[4], mki2[4];
            #pragma unroll
            for (int ii = 0; ii < 4; ii++) {
                int i = ib + ii;
                mij2[ii] = __float2half2_rn(met[i * 16 + j]);
                mki2[ii] = __float2half2_rn(met[i * 16 + k]);  // symmetric
            }
            float facc[4];
            #pragma unroll
            for (int ii = 0; ii < 4; ii++) facc[ii] = c0;

            #pragma unroll
            for (int blk = 0; blk < 8; blk++) {
                __half2 acc[4];
                #pragma unroll
                for (int ii = 0; ii < 4; ii++) acc[ii] = z2;
                #pragma unroll
                for (int r = 0; r < 8; r++) {
                    int q = blk * 8 + r;
                    WPack w = sW[q];
                    __half2 v = sV[q];
                    #pragma unroll
                    for (int ii = 0; ii < 4; ii++) {
                        __half2 x = __hfma2(mij2[ii], w.w0, w.b);
                        x = __hfma2(mjk2, w.w1, x);
                        x = __hfma2(mki2[ii], w.w2, x);
                        acc[ii] = __hfma2(v, tanh2h(x), acc[ii]);
                    }
                }
                #pragma unroll
                for (int ii = 0; ii < 4; ii++) {
                    float2 f = __half22float2(acc[ii]);
                    facc[ii] += f.x + f.y;
                }
            }
            #pragma unroll
            for (int ii = 0; ii < 4; ii++)
                chs[ib + ii][o] = __float2half(facc[ii]);
        }
    }
    __syncthreads();   // orders chs, pms, m2s for Stage B

    // ---- P5 Stage B: ricci hidden sums, 2 chunks of 4 i's, all 16 j ----
    {
        const float* rW1c = rW1 + 48 * 256;
        __half2 rwh[8];
        #pragma unroll
        for (int q = 0; q < 8; q++)
            rwh[q] = __floats2half2_rn(rW1c[(2 * q) * 256 + o],
                                       rW1c[(2 * q + 1) * 256 + o]);
        const __half2 z2 = __float2half2_rn(0.0f);
        float ssum = 0.0f;

        #pragma unroll
        for (int c = 0; c < 2; c++) {
            int ib = hi * 8 + c * 4;
            float pm[4], s[4];
            #pragma unroll
            for (int ii = 0; ii < 4; ii++) {
                pm[ii] = pms[ib + ii][o];
                s[ii] = 0.0f;
            }

            #pragma unroll 2
            for (int j = 0; j < ND; j++) {
                float m2 = m2s[j][o];
                #pragma unroll
                for (int ii = 0; ii < 4; ii++) {
                    const uint4* cp = (const uint4*)&chs[ib + ii][j * 16];
                    uint4 u0 = cp[0];
                    uint4 u1 = cp[1];
                    __half2 acc = z2;
                    acc = __hfma2(u2h2(u0.x), rwh[0], acc);
                    acc = __hfma2(u2h2(u0.y), rwh[1], acc);
                    acc = __hfma2(u2h2(u0.z), rwh[2], acc);
                    acc = __hfma2(u2h2(u0.w), rwh[3], acc);
                    acc = __hfma2(u2h2(u1.x), rwh[4], acc);
                    acc = __hfma2(u2h2(u1.y), rwh[5], acc);
                    acc = __hfma2(u2h2(u1.z), rwh[6], acc);
                    acc = __hfma2(u2h2(u1.w), rwh[7], acc);
                    float2 f = __half22float2(acc);
                    float a = pm[ii] + m2 + f.x + f.y;
                    s[ii] += fmaxf(a, 0.0f);
                }
            }
            ssum += ((s[0] + s[1]) + (s[2] + s[3]));
        }
        red[hi][o] = ssum;
    }
    __syncthreads();
    if (t < 256) Ss[t] = (red[0][t] + red[1][t]) * (1.0f / 256.0f);
    __syncthreads();

    // ---- P6: output GEMM (h in [hi*128, hi*128+128), 2 interleaved chains) ----
    {
        int h0 = hi * 128;
        float a0 = 0.f, a1 = 0.f;
        #pragma unroll 8
        for (int h = 0; h < 64; h++) {
            a0 = fmaf(Ss[h0 + h],      rW2[(h0 + h) * 256 + o],      a0);
            a1 = fmaf(Ss[h0 + 64 + h], rW2[(h0 + 64 + h) * 256 + o], a1);
        }
        red[hi][o] = a0 + a1;
    }
    __syncthreads();
    if (t < 256) buf[t] = rb2[t] + red[0][t] + red[1][t];
    __syncthreads();
    if (t < 256) {
        int i = t >> 4, j = t & 15;
        out[b * 256 + t] = 0.5f * (buf[i * 16 + j] + buf[j * 16 + i]);
    }
}

// ============================================================================
extern "C" void kernel_launch(void* const* d_in, const int* in_sizes, int n_in,
                              void* d_out, int out_size)
{
    const float* points = (const float*)d_in[0];
    const float* mW1    = (const float*)d_in[1];
    const float* mb1    = (const float*)d_in[2];
    const float* mW2    = (const float*)d_in[3];
    const float* mb2    = (const float*)d_in[4];
    const float* cW1    = (const float*)d_in[5];
    const float* cb1    = (const float*)d_in[6];
    const float* cW2    = (const float*)d_in[7];
    const float* cb2    = (const float*)d_in[8];
    const float* rW1    = (const float*)d_in[9];
    const float* rb1    = (const float*)d_in[10];
    const float* rW2    = (const float*)d_in[11];
    const float* rb2    = (const float*)d_in[12];
    float* out = (float*)d_out;

    k_all<<<NB, 512>>>(points, mW1, mb1, mW2, mb2,
                       cW1, cb1, cW2, cb2, rW1, rb1, rW2, rb2, out);
}

// round 17
// speedup vs baseline: 5.6811x; 5.6811x over previous
#include <cuda_runtime.h>
#include <cuda_fp16.h>
#include <cstdint>

#define NB 256   // batch
#define ND 16    // manifold dim
#define NH 128   // hidden
#define IPB 4    // i's per block in k_main

// ---- scratch (device globals; no allocation) ----
__device__ float g_metric[NB * 256];          // metric[b][i*16+j]
__device__ float g_PB[NB * 256];              // points@rW1[0:16] + rb1
__device__ float g_M1[NB * ND * 256];         // M1[b][i][o]
__device__ float g_M2[NB * ND * 256];         // M2[b][j][o]
__device__ float g_Spart4[NB * 4 * 256];      // per-(b, i-quad) reduced sums

__device__ __forceinline__ __half2 tanh2h(__half2 x) {
    uint32_t xi, yi;
    xi = *reinterpret_cast<uint32_t*>(&x);
    asm("tanh.approx.f16x2 %0, %1;" : "=r"(yi) : "r"(xi));
    __half2 y = *reinterpret_cast<__half2*>(&yi);
    return y;
}
__device__ __forceinline__ __half2 u2h2(uint32_t u) {
    return *reinterpret_cast<__half2*>(&u);
}

// ============================================================================
// K1: metric + PB + M1/M2.  grid=NB, 1024 threads.  (R9 verbatim)
// ============================================================================
__global__ __launch_bounds__(1024) void k_metric(
    const float* __restrict__ points,
    const float* __restrict__ mW1, const float* __restrict__ mb1,
    const float* __restrict__ mW2, const float* __restrict__ mb2,
    const float* __restrict__ rW1, const float* __restrict__ rb1)
{
    int b = blockIdx.x;
    int t = threadIdx.x;
    int g2 = t >> 8, o = t & 255;

    __shared__ float pts[ND];
    __shared__ float mh[NH];
    __shared__ __align__(16) float part[16][256];
    __shared__ float met[256];

    float rwA[ND], rwB[ND];
    #pragma unroll
    for (int p = 0; p < ND; p++) {
        rwA[p] = rW1[(16 + p) * 256 + o];
        rwB[p] = rW1[(32 + p) * 256 + o];
    }

    if (t < ND) pts[t] = points[b * ND + t];
    __syncthreads();

    if (t < NH) {
        float a = mb1[t];
        #pragma unroll
        for (int p = 0; p < ND; p++) a = fmaf(pts[p], mW1[p * NH + t], a);
        mh[t] = fmaxf(a, 0.0f);
    }
    __syncthreads();

    {
        int g = t >> 6, q = t & 63;
        float4 acc = make_float4(0.f, 0.f, 0.f, 0.f);
        #pragma unroll
        for (int h = 0; h < 8; h++) {
            int hh = g * 8 + h;
            float4 w = *(const float4*)&mW2[hh * 256 + 4 * q];
            float m = mh[hh];
            acc.x = fmaf(m, w.x, acc.x);
            acc.y = fmaf(m, w.y, acc.y);
            acc.z = fmaf(m, w.z, acc.z);
            acc.w = fmaf(m, w.w, acc.w);
        }
        *(float4*)&part[g][4 * q] = acc;
    }
    __syncthreads();

    if (t < 256) {
        float a = mb2[t];
        #pragma unroll
        for (int g = 0; g < 16; g++) a += part[g][t];
        part[0][t] = a;
    }
    __syncthreads();

    if (t < 256) {
        int i = t >> 4, j = t & 15;
        float m = 0.5f * (part[0][i * 16 + j] + part[0][j * 16 + i])
                + (i == j ? 1e-6f : 0.0f);
        met[t] = m;
        g_metric[b * 256 + t] = m;
        float a = rb1[t];
        #pragma unroll
        for (int p = 0; p < ND; p++) a = fmaf(pts[p], rW1[p * 256 + t], a);
        g_PB[b * 256 + t] = a;
    }
    __syncthreads();

    #pragma unroll
    for (int ii = 0; ii < 4; ii++) {
        int i0 = g2 * 4 + ii;
        float a1 = 0.0f, a2 = 0.0f;
        #pragma unroll
        for (int p = 0; p < ND; p++) {
            float mv = met[i0 * 16 + p];
            a1 = fmaf(mv, rwA[p], a1);
            a2 = fmaf(mv, rwB[p], a2);
        }
        g_M1[(b * ND + i0) * 256 + o] = a1;
        g_M2[(b * ND + i0) * 256 + o] = a2;
    }
}

// ============================================================================
// K2: main fused kernel.  (R9 verbatim except the pre-reduced Spart4 store)
// ============================================================================
struct WPack { __half2 w0, w1, w2, b; };   // 16 bytes

__global__ __launch_bounds__(256) void k_main(
    const float* __restrict__ cW1, const float* __restrict__ cb1,
    const float* __restrict__ cW2, const float* __restrict__ cb2,
    const float* __restrict__ rW1)
{
    int x  = blockIdx.x;        // i-quad index 0..3
    int i0 = x * IPB;           // 0,4,8,12
    int b  = blockIdx.y;        // 0..255
    int t  = threadIdx.x;       // 0..255

    __shared__ float met[256];
    __shared__ __align__(16) WPack   sW[NH / 2];
    __shared__ __align__(4)  __half2 sV[NH / 2];
    __shared__ __align__(16) __half  chs[IPB][256];

    met[t] = g_metric[b * 256 + t];
    if (t < NH / 2) {
        int q = t;
        WPack w;
        w.w0 = __floats2half2_rn(cW1[2 * q],          cW1[2 * q + 1]);
        w.w1 = __floats2half2_rn(cW1[NH + 2 * q],     cW1[NH + 2 * q + 1]);
        w.w2 = __floats2half2_rn(cW1[2 * NH + 2 * q], cW1[2 * NH + 2 * q + 1]);
        w.b  = __floats2half2_rn(cb1[2 * q],          cb1[2 * q + 1]);
        sW[q] = w;
        sV[q] = __floats2half2_rn(cW2[2 * q], cW2[2 * q + 1]);
    }
    __syncthreads();

    // ---- Stage A: christoffel for (i0..i0+3, j=t>>4, k=t&15) ----
    {
        int j = t >> 4, k = t & 15;
        __half2 mjk2 = __float2half2_rn(met[j * 16 + k]);
        __half2 mij2[IPB], mki2[IPB];
        #pragma unroll
        for (int ii = 0; ii < IPB; ii++) {
            mij2[ii] = __float2half2_rn(met[(i0 + ii) * 16 + j]);
            mki2[ii] = __float2half2_rn(met[(i0 + ii) * 16 + k]);  // symmetric
        }
        const __half2 z2 = __float2half2_rn(0.0f);

        float facc[IPB];
        #pragma unroll
        for (int ii = 0; ii < IPB; ii++) facc[ii] = cb2[0];

        #pragma unroll
        for (int blk = 0; blk < 8; blk++) {
            __half2 acc[IPB];
            #pragma unroll
            for (int ii = 0; ii < IPB; ii++) acc[ii] = z2;
            #pragma unroll
            for (int r = 0; r < 8; r++) {
                int q = blk * 8 + r;
                WPack w = sW[q];
                __half2 v = sV[q];
                #pragma unroll
                for (int ii = 0; ii < IPB; ii++) {
                    __half2 xh = __hfma2(mij2[ii], w.w0, w.b);
                    xh = __hfma2(mjk2, w.w1, xh);
                    xh = __hfma2(mki2[ii], w.w2, xh);
                    acc[ii] = __hfma2(v, tanh2h(xh), acc[ii]);
                }
            }
            #pragma unroll
            for (int ii = 0; ii < IPB; ii++) {
                float2 f = __half22float2(acc[ii]);
                facc[ii] += f.x + f.y;
            }
        }
        #pragma unroll
        for (int ii = 0; ii < IPB; ii++)
            chs[ii][t] = __float2half(facc[ii]);
    }
    __syncthreads();

    // ---- Stage B: hidden layer of ricci net, reduced over j, 4 i's ----
    {
        int o = t;
        const float* rW1c = rW1 + 48 * 256;
        __half2 rwh[8];
        #pragma unroll
        for (int q = 0; q < 8; q++)
            rwh[q] = __floats2half2_rn(rW1c[(2 * q) * 256 + o],
                                       rW1c[(2 * q + 1) * 256 + o]);

        float pm[IPB], s[IPB];
        float pb = g_PB[b * 256 + o];
        #pragma unroll
        for (int ii = 0; ii < IPB; ii++) {
            pm[ii] = pb + g_M1[(b * ND + i0 + ii) * 256 + o];
            s[ii] = 0.0f;
        }
        const __half2 z2 = __float2half2_rn(0.0f);

        #pragma unroll 4
        for (int j = 0; j < ND; j++) {
            float m2 = g_M2[(b * ND + j) * 256 + o];
            #pragma unroll
            for (int ii = 0; ii < IPB; ii++) {
                const uint4* cp = (const uint4*)&chs[ii][j * 16];
                uint4 u0 = cp[0];
                uint4 u1 = cp[1];
                __half2 acc = z2;
                acc = __hfma2(u2h2(u0.x), rwh[0], acc);
                acc = __hfma2(u2h2(u0.y), rwh[1], acc);
                acc = __hfma2(u2h2(u0.z), rwh[2], acc);
                acc = __hfma2(u2h2(u0.w), rwh[3], acc);
                acc = __hfma2(u2h2(u1.x), rwh[4], acc);
                acc = __hfma2(u2h2(u1.y), rwh[5], acc);
                acc = __hfma2(u2h2(u1.z), rwh[6], acc);
                acc = __hfma2(u2h2(u1.w), rwh[7], acc);
                float2 f = __half22float2(acc);
                float a = pm[ii] + m2 + f.x + f.y;
                s[ii] += fmaxf(a, 0.0f);
            }
        }
        // pre-reduced store: one STG per thread, k_final loads 4 not 16
        g_Spart4[(b * 4 + x) * 256 + o] = (s[0] + s[1]) + (s[2] + s[3]);
    }
}

// ============================================================================
// K3: Ss reduce + output GEMM + symmetrize, grid=NB, 1024 threads.
//     4 h-groups x 256 o; short chains; sym in-block.
// ============================================================================
__global__ __launch_bounds__(1024) void k_final(
    const float* __restrict__ rW2, const float* __restrict__ rb2,
    float* __restrict__ out)
{
    int b  = blockIdx.x;
    int t  = threadIdx.x;      // 0..1023
    int o  = t & 255;
    int hg = t >> 8;           // 0..3

    __shared__ float Ss[256];
    __shared__ float red[4][256];
    __shared__ float raw[256];

    if (t < 256) {
        const float* sp = &g_Spart4[b * 4 * 256 + t];
        float s = (sp[0] + sp[256]) + (sp[512] + sp[768]);
        Ss[t] = s * (1.0f / 256.0f);
    }
    __syncthreads();

    // h-group hg covers h in [64*hg, 64*hg+64), 2 interleaved chains
    {
        int h0 = hg * 64;
        float a0 = 0.f, a1 = 0.f;
        #pragma unroll 8
        for (int h = 0; h < 32; h++) {
            a0 = fmaf(Ss[h0 + h],      rW2[(h0 + h) * 256 + o],      a0);
            a1 = fmaf(Ss[h0 + 32 + h], rW2[(h0 + 32 + h) * 256 + o], a1);
        }
        red[hg][o] = a0 + a1;
    }
    __syncthreads();

    if (t < 256) {
        raw[t] = rb2[t] + (red[0][t] + red[1][t]) + (red[2][t] + red[3][t]);
    }
    __syncthreads();

    if (t < 256) {
        int i = t >> 4, j = t & 15;
        out[b * 256 + t] = 0.5f * (raw[i * 16 + j] + raw[j * 16 + i]);
    }
}

// ============================================================================
extern "C" void kernel_launch(void* const* d_in, const int* in_sizes, int n_in,
                              void* d_out, int out_size)
{
    const float* points = (const float*)d_in[0];
    const float* mW1    = (const float*)d_in[1];
    const float* mb1    = (const float*)d_in[2];
    const float* mW2    = (const float*)d_in[3];
    const float* mb2    = (const float*)d_in[4];
    const float* cW1    = (const float*)d_in[5];
    const float* cb1    = (const float*)d_in[6];
    const float* cW2    = (const float*)d_in[7];
    const float* cb2    = (const float*)d_in[8];
    const float* rW1    = (const float*)d_in[9];
    const float* rb1    = (const float*)d_in[10];
    const float* rW2    = (const float*)d_in[11];
    const float* rb2    = (const float*)d_in[12];
    float* out = (float*)d_out;

    k_metric<<<NB, 1024>>>(points, mW1, mb1, mW2, mb2, rW1, rb1);
    dim3 grid2(ND / IPB, NB);
    k_main<<<grid2, 256>>>(cW1, cb1, cW2, cb2, rW1);
    k_final<<<NB, 1024>>>(rW2, rb2, out);
}